// round 10
// baseline (speedup 1.0000x reference)
#include <cuda_runtime.h>
#include <cuda_fp16.h>
#include <math.h>
#include <stdint.h>

#define BSZ   4
#define TLEN  2048
#define CDIM  1024
#define NHEAD 16
#define HD    64

#define SCRATCH_ELEMS (BSZ * NHEAD * TLEN * HD)   // 8,388,608
#define XN (BSZ * TLEN * CDIM)
#define WN (3 * CDIM * CDIM)

// g_q, g_k: fp16 [bh][t][d'] with d' quad-interleaved within 16-blocks
//           ({2c,2c+1,2c+8,2c+9} -> {4c..4c+3}); Q pre-scaled by 0.125*log2e.
// g_v:      fp16 TRANSPOSED [bh][d][t'] with t' quad-interleaved likewise.
// g_xt/g_wt: x / W as fp16 with k-dim quad-interleaved.
__device__ __half g_q[SCRATCH_ELEMS];
__device__ __half g_k[SCRATCH_ELEMS];
__device__ __half g_v[SCRATCH_ELEMS];
__device__ __half g_xt[XN];
__device__ __half g_wt[WN];

// ===========================================================================
// Helpers
// ===========================================================================
__device__ __forceinline__ uint32_t smem_u32(const void* p) {
    uint32_t a;
    asm("{ .reg .u64 t; cvta.to.shared.u64 t, %1; cvt.u32.u64 %0, t; }"
        : "=r"(a) : "l"(p));
    return a;
}

__device__ __forceinline__ void cp_async16(uint32_t saddr, const void* gaddr) {
    asm volatile("cp.async.cg.shared.global [%0], [%1], 16;"
                 :: "r"(saddr), "l"(gaddr) : "memory");
}
__device__ __forceinline__ void cp_async_commit() {
    asm volatile("cp.async.commit_group;" ::: "memory");
}
template <int N>
__device__ __forceinline__ void cp_async_wait() {
    asm volatile("cp.async.wait_group %0;" :: "n"(N) : "memory");
}

__device__ __forceinline__ float ex2f(float x) {
    float y;
    asm("ex2.approx.ftz.f32 %0, %1;" : "=f"(y) : "f"(x));
    return y;
}

// D(16x8) += A(16x16 row) * B(16x8 col), fp16 in, fp32 accumulate
__device__ __forceinline__ void mma_16816_f16(
    float* d, uint32_t a0, uint32_t a1, uint32_t a2, uint32_t a3,
    uint32_t b0, uint32_t b1)
{
    asm volatile(
        "mma.sync.aligned.m16n8k16.row.col.f32.f16.f16.f32 "
        "{%0,%1,%2,%3}, {%4,%5,%6,%7}, {%8,%9}, {%0,%1,%2,%3};"
        : "+f"(d[0]), "+f"(d[1]), "+f"(d[2]), "+f"(d[3])
        : "r"(a0), "r"(a1), "r"(a2), "r"(a3), "r"(b0), "r"(b1));
}

// quad-interleave within 16-block: k -> 4*((k&7)>>1) + 2*((k>>3)&1) + (k&1)
__device__ __forceinline__ int qperm(int k) {
    return (k & ~15) + 4 * ((k & 7) >> 1) + 2 * ((k >> 3) & 1) + (k & 1);
}

__device__ __forceinline__ uint32_t h2u(half2 h) {
    return *(uint32_t*)&h;
}

// ===========================================================================
// Kernel 0: convert x and W to fp16 with k-quad-interleave.
// One 16-element block per thread: 4x16B coalesced loads, 2x16B coalesced
// stores; the interleave permutation is folded into register packing.
// ===========================================================================
#define NCVT16 ((XN + WN) / 16)     // 720,896 blocks of 16

__global__ void __launch_bounds__(256) cvt_kernel(
    const float* __restrict__ x, const float* __restrict__ w)
{
    const int nx16 = XN / 16;
    const int i = blockIdx.x * blockDim.x + threadIdx.x;
    if (i >= NCVT16) return;

    const float4* src;
    __half* dst;
    if (i < nx16) { src = (const float4*)x + (size_t)i * 4;          dst = g_xt + (size_t)i * 16; }
    else          { src = (const float4*)w + (size_t)(i - nx16) * 4; dst = g_wt + (size_t)(i - nx16) * 16; }

    const float4 v0 = src[0], v1 = src[1], v2 = src[2], v3 = src[3];
    // qperm: k(0,1)->d(0,1)  k(2,3)->d(4,5)  k(4,5)->d(8,9)   k(6,7)->d(12,13)
    //        k(8,9)->d(2,3)  k(10,11)->d(6,7) k(12,13)->d(10,11) k(14,15)->d(14,15)
    uint4 o0, o1;
    o0.x = h2u(__floats2half2_rn(v0.x, v0.y));   // d0,1   <- k0,1
    o0.y = h2u(__floats2half2_rn(v2.x, v2.y));   // d2,3   <- k8,9
    o0.z = h2u(__floats2half2_rn(v0.z, v0.w));   // d4,5   <- k2,3
    o0.w = h2u(__floats2half2_rn(v2.z, v2.w));   // d6,7   <- k10,11
    o1.x = h2u(__floats2half2_rn(v1.x, v1.y));   // d8,9   <- k4,5
    o1.y = h2u(__floats2half2_rn(v3.x, v3.y));   // d10,11 <- k12,13
    o1.z = h2u(__floats2half2_rn(v1.z, v1.w));   // d12,13 <- k6,7
    o1.w = h2u(__floats2half2_rn(v3.z, v3.w));   // d14,15 <- k14,15
    *(uint4*)(dst)     = o0;
    *(uint4*)(dst + 8) = o1;
}

// ===========================================================================
// Kernel 1: QKV projection, fp16 m16n8k16. CTA 128x128, warp 32x64, TK=32.
// 4-stage pipeline, issue-first + wait<3> -> 3 outstanding chunk loads.
// ===========================================================================
#define TM 128
#define TN 128
#define NSTG 4
#define LDH 48                                // halves per row (only 32 used)
#define A_STG_H (TM * LDH)                    // 6144 halves
#define STG_H   (2 * A_STG_H)                 // A + B
#define NCHUNK (CDIM / 32)                    // 32
#define DYN_SMEM (NSTG * STG_H * 2)           // 98304 B
#define Q_PRESCALE (0.125f * 1.44269504f)

__global__ void __launch_bounds__(256, 2) qkv_mma_kernel(
    const float* __restrict__ bias)
{
    extern __shared__ __half smh[];

    const int tid = threadIdx.x;
    const int wid = tid >> 5;
    const int lid = tid & 31;
    const int g   = lid >> 2;
    const int c   = lid & 3;
    const int warp_m = (wid & 3) * 32;
    const int warp_n = (wid >> 2) * 64;
    const int m0  = blockIdx.y * TM;
    const int n0  = blockIdx.x * TN;

    const uint32_t sbase = smem_u32(smh);

    // cp.async mapping: 1024 x 16B chunks per stage, 4 per thread
    const char* gptr[4];
    uint32_t    soff[4];
#pragma unroll
    for (int t = 0; t < 4; t++) {
        const int cc = tid + t * 256;
        if (cc < 512) {
            const int row = cc >> 2, o = cc & 3;
            gptr[t] = (const char*)(g_xt + (size_t)(m0 + row) * CDIM) + o * 16;
            soff[t] = (uint32_t)(row * LDH * 2 + o * 16);
        } else {
            const int cb = cc - 512;
            const int row = cb >> 2, o = cb & 3;
            gptr[t] = (const char*)(g_wt + (size_t)(n0 + row) * CDIM) + o * 16;
            soff[t] = (uint32_t)(A_STG_H * 2 + row * LDH * 2 + o * 16);
        }
    }

#define LOAD_STAGE(chunk)                                                   \
    do {                                                                    \
        const uint32_t sb_ = sbase + ((chunk) % NSTG) * (STG_H * 2);        \
        const int gof_ = (chunk) * 64;   /* 32 halves */                    \
        _Pragma("unroll")                                                   \
        for (int t = 0; t < 4; t++)                                         \
            cp_async16(sb_ + soff[t], gptr[t] + gof_);                      \
        cp_async_commit();                                                  \
    } while (0)

    float acc[2][8][4];
#pragma unroll
    for (int mb = 0; mb < 2; mb++)
#pragma unroll
        for (int nb = 0; nb < 8; nb++)
#pragma unroll
            for (int r = 0; r < 4; r++) acc[mb][nb][r] = 0.f;

    LOAD_STAGE(0);
    LOAD_STAGE(1);
    LOAD_STAGE(2);

    for (int i = 0; i < NCHUNK; i++) {
        // issue FIRST (buffer (i+3)%4 == (i-1)%4, consumed last iter), then
        // wait<3>: newest 3 groups may be pending -> chunk i landed.
        if (i + 3 < NCHUNK) { LOAD_STAGE(i + 3); }
        else                { cp_async_commit(); }
        cp_async_wait<NSTG - 1>();
        __syncthreads();

        const __half* As = smh + (i % NSTG) * STG_H;
        const __half* Bs = As + A_STG_H;

#pragma unroll
        for (int ks = 0; ks < 2; ks++) {        // two k16 steps per 32-chunk
            const int ho = ks * 16 + 4 * c;     // interleaved quad offset
            uint32_t afl[2][2], afh[2][2];
#pragma unroll
            for (int mb = 0; mb < 2; mb++) {
                const uint2 lo = *(const uint2*)(As + (warp_m + mb * 16 + g) * LDH + ho);
                const uint2 hi = *(const uint2*)(As + (warp_m + mb * 16 + g + 8) * LDH + ho);
                afl[mb][0] = lo.x; afl[mb][1] = lo.y;   // a0, a2
                afh[mb][0] = hi.x; afh[mb][1] = hi.y;   // a1, a3
            }
            uint32_t bf[8][2];
#pragma unroll
            for (int nb = 0; nb < 8; nb++) {
                const uint2 bb = *(const uint2*)(Bs + (warp_n + nb * 8 + g) * LDH + ho);
                bf[nb][0] = bb.x; bf[nb][1] = bb.y;
            }
#pragma unroll
            for (int mb = 0; mb < 2; mb++)
#pragma unroll
                for (int nb = 0; nb < 8; nb++)
                    mma_16816_f16(acc[mb][nb],
                                  afl[mb][0], afh[mb][0], afl[mb][1], afh[mb][1],
                                  bf[nb][0], bf[nb][1]);
        }
        __syncthreads();
    }

    // ---- epilogue ----
    const int which = n0 >> 10;                 // 0=Q 1=K 2=V

#pragma unroll
    for (int mb = 0; mb < 2; mb++) {
        const int mA = m0 + warp_m + mb * 16 + g;
        const int mB = mA + 8;
        const int bA = mA >> 11, tA = mA & (TLEN - 1);
        const int bB = mB >> 11, tB = mB & (TLEN - 1);
#pragma unroll
        for (int nb = 0; nb < 8; nb++) {
            const int n = n0 + warp_n + nb * 8 + 2 * c;
            const int h = (n >> 6) & (NHEAD - 1);
            const int d = n & 63;
            const float bx = __ldg(bias + n);
            const float by = __ldg(bias + n + 1);

            if (which == 2) {
                // V^T: [bh][d][t'], t' quad-interleaved
                const int ptA = qperm(tA);
                const int ptB = qperm(tB);
                __half* baseA = g_v + ((size_t)(bA * NHEAD + h) * HD) * TLEN;
                __half* baseB = g_v + ((size_t)(bB * NHEAD + h) * HD) * TLEN;
                baseA[(size_t)d * TLEN + ptA]       = __float2half_rn(acc[mb][nb][0] + bx);
                baseA[(size_t)(d + 1) * TLEN + ptA] = __float2half_rn(acc[mb][nb][1] + by);
                baseB[(size_t)d * TLEN + ptB]       = __float2half_rn(acc[mb][nb][2] + bx);
                baseB[(size_t)(d + 1) * TLEN + ptB] = __float2half_rn(acc[mb][nb][3] + by);
            } else {
                __half* dst = (which == 0) ? g_q : g_k;
                const float sc = (which == 0) ? Q_PRESCALE : 1.0f;
                const int pd = qperm(d);        // d even -> pd, pd+1 adjacent
                __half* pA = dst + (((size_t)(bA * NHEAD + h) * TLEN) + tA) * HD + pd;
                __half* pB = dst + (((size_t)(bB * NHEAD + h) * TLEN) + tB) * HD + pd;
                *(half2*)pA = __floats2half2_rn((acc[mb][nb][0] + bx) * sc,
                                                (acc[mb][nb][1] + by) * sc);
                *(half2*)pB = __floats2half2_rn((acc[mb][nb][2] + bx) * sc,
                                                (acc[mb][nb][3] + by) * sc);
            }
        }
    }
}

// ===========================================================================
// Kernel 2: fp16 TC causal flash attention.
//   CTA = 8 warps = 128 q rows; K/V tiles of 128 keys (two 64-key halves),
//   double-buffered cp.async; Q tile resident in smem. 2 CTAs/SM.
//   Diagonal tiles skip fully-masked 8/16-key blocks (exact: P == 0 there).
// ===========================================================================
#define ATM 128
#define ATK 128
#define QSTR 80                        // halves per Q/K row (160 B)
#define KSTR 80
#define VSTR 144                       // halves per V^T row (288 B)
#define QT_H (ATM * QSTR)              // 10240
#define KT_H (ATK * KSTR)              // 10240
#define VT_H (HD * VSTR)               // 9216
#define BUF_H (KT_H + VT_H)            // 19456
#define ATTN_SMEM ((QT_H + 2 * BUF_H) * 2)   // 98304 B

__global__ void __launch_bounds__(256, 2) attn_tc_kernel(float* __restrict__ out)
{
    extern __shared__ __half smh[];
    __half* SQ = smh;
    __half* SB = smh + QT_H;

    const int tid  = threadIdx.x;
    const int wid  = tid >> 5;
    const int lane = tid & 31;
    const int g    = lane >> 2;
    const int c    = lane & 3;
    const int bh   = blockIdx.y;
    const int b    = bh >> 4;
    const int h    = bh & (NHEAD - 1);
    const int q0   = (gridDim.x - 1 - blockIdx.x) * ATM;   // heavy first
    const int r0l  = wid * 16 + g;
    const int r0   = q0 + r0l;
    const int r1   = r0 + 8;
    const int rmax = q0 + wid * 16 + 15;    // warp-uniform max q row

    const __half* qb  = g_q + (size_t)bh * TLEN * HD;
    const __half* kb  = g_k + (size_t)bh * TLEN * HD;
    const __half* vtb = g_v + (size_t)bh * HD * TLEN;

    // ---- Q tile: 128 rows x 128 B (8 chunks/row), 4 chunks/thread ----
    {
        const uint32_t qd = smem_u32(SQ);
#pragma unroll
        for (int i = 0; i < 4; i++) {
            const int id  = tid + i * 256;
            const int row = id >> 3;
            const int o   = id & 7;
            cp_async16(qd + (uint32_t)(row * QSTR * 2 + o * 16),
                       qb + (size_t)(q0 + row) * HD + o * 8);
        }
        cp_async_commit();
    }

    float o[8][4];
#pragma unroll
    for (int nb = 0; nb < 8; nb++)
#pragma unroll
        for (int r = 0; r < 4; r++) o[nb][r] = 0.f;
    float mrow0 = -1e30f, mrow1 = -1e30f;
    float lrow0 = 0.f,    lrow1 = 0.f;

    const int nkt = q0 / ATK + 1;

    // K: 128 keys x 128 B (8 chunks/row); V^T: 64 d x 256 B (16 chunks/row)
#define ATTN_LOAD(kt)                                                        \
    do {                                                                     \
        const int j0_ = (kt) * ATK;                                          \
        const uint32_t sd_ = smem_u32(SB) + ((kt) & 1) * (BUF_H * 2);        \
        _Pragma("unroll")                                                    \
        for (int i_ = 0; i_ < 8; i_++) {                                     \
            const int id_ = tid + i_ * 256;                                  \
            const __half* src_;                                              \
            uint32_t dst_;                                                   \
            if (id_ < 1024) {                                                \
                const int row_ = id_ >> 3, o_ = id_ & 7;                     \
                src_ = kb + (size_t)(j0_ + row_) * HD + o_ * 8;              \
                dst_ = sd_ + (uint32_t)(row_ * KSTR * 2 + o_ * 16);          \
            } else {                                                         \
                const int id2_ = id_ - 1024;                                 \
                const int row_ = id2_ >> 4, o_ = id2_ & 15;                  \
                src_ = vtb + (size_t)row_ * TLEN + j0_ + o_ * 8;             \
                dst_ = sd_ + KT_H * 2                                        \
                     + (uint32_t)(row_ * VSTR * 2 + o_ * 16);                \
            }                                                                \
            cp_async16(dst_, src_);                                          \
        }                                                                    \
        cp_async_commit();                                                   \
    } while (0)

    ATTN_LOAD(0);

    for (int kt = 0; kt < nkt; kt++) {
        if (kt + 1 < nkt) { ATTN_LOAD(kt + 1); cp_async_wait<1>(); }
        else              { cp_async_wait<0>(); }
        __syncthreads();

        const __half* SK = SB + (kt & 1) * BUF_H;
        const __half* SV = SK + KT_H;
        const bool last = (kt == nkt - 1);

#pragma unroll
        for (int hf = 0; hf < 2; hf++) {
            const int j0h = kt * ATK + hf * 64;
            if (j0h > rmax) break;              // warp fully masked

            // ---- S = Q K^T (16 x 64), skipping fully-masked 8-key blocks ----
            float s[8][4];
#pragma unroll
            for (int nb = 0; nb < 8; nb++)
#pragma unroll
                for (int r = 0; r < 4; r++) s[nb][r] = 0.f;

#pragma unroll
            for (int ks = 0; ks < 4; ks++) {
                const int ho = ks * 16 + 4 * c;
                const uint2 qA = *(const uint2*)(SQ + r0l * QSTR + ho);
                const uint2 qB = *(const uint2*)(SQ + (r0l + 8) * QSTR + ho);
#pragma unroll
                for (int nb = 0; nb < 8; nb++) {
                    if (!last || (j0h + nb * 8 <= rmax)) {
                        const uint2 kk = *(const uint2*)(SK + (hf * 64 + nb * 8 + g) * KSTR + ho);
                        mma_16816_f16(s[nb], qA.x, qB.x, qA.y, qB.y, kk.x, kk.y);
                    }
                }
            }

            // ---- causal mask (last tile only; also masks skipped blocks) ----
            if (last) {
#pragma unroll
                for (int nb = 0; nb < 8; nb++) {
                    const int jA = j0h + nb * 8 + 2 * c;
                    if (jA     > r0) s[nb][0] = -1e30f;
                    if (jA + 1 > r0) s[nb][1] = -1e30f;
                    if (jA     > r1) s[nb][2] = -1e30f;
                    if (jA + 1 > r1) s[nb][3] = -1e30f;
                }
            }

            // ---- online softmax (base 2) ----
            float t0 = -1e30f, t1 = -1e30f;
#pragma unroll
            for (int nb = 0; nb < 8; nb++) {
                t0 = fmaxf(t0, fmaxf(s[nb][0], s[nb][1]));
                t1 = fmaxf(t1, fmaxf(s[nb][2], s[nb][3]));
            }
            t0 = fmaxf(t0, __shfl_xor_sync(0xffffffffu, t0, 1));
            t0 = fmaxf(t0, __shfl_xor_sync(0xffffffffu, t0, 2));
            t1 = fmaxf(t1, __shfl_xor_sync(0xffffffffu, t1, 1));
            t1 = fmaxf(t1, __shfl_xor_sync(0xffffffffu, t1, 2));

            const float mn0 = fmaxf(mrow0, t0);
            const float mn1 = fmaxf(mrow1, t1);
            const float a0s = ex2f(mrow0 - mn0);
            const float a1s = ex2f(mrow1 - mn1);
            mrow0 = mn0; mrow1 = mn1;
            lrow0 *= a0s; lrow1 *= a1s;
#pragma unroll
            for (int nb = 0; nb < 8; nb++) {
                o[nb][0] *= a0s; o[nb][1] *= a0s;
                o[nb][2] *= a1s; o[nb][3] *= a1s;
            }

#pragma unroll
            for (int nb = 0; nb < 8; nb++) {
                s[nb][0] = ex2f(s[nb][0] - mn0);
                s[nb][1] = ex2f(s[nb][1] - mn0);
                s[nb][2] = ex2f(s[nb][2] - mn1);
                s[nb][3] = ex2f(s[nb][3] - mn1);
                lrow0 += s[nb][0] + s[nb][1];
                lrow1 += s[nb][2] + s[nb][3];
            }

            // ---- O += P V, skipping fully-masked 16-key blocks (P == 0) ----
#pragma unroll
            for (int kbk = 0; kbk < 4; kbk++) {     // 4 k16 blocks of keys
                if (!last || (j0h + kbk * 16 <= rmax)) {
                    const uint32_t pa0 = h2u(__floats2half2_rn(s[2*kbk][0],   s[2*kbk][1]));
                    const uint32_t pa1 = h2u(__floats2half2_rn(s[2*kbk][2],   s[2*kbk][3]));
                    const uint32_t pa2 = h2u(__floats2half2_rn(s[2*kbk+1][0], s[2*kbk+1][1]));
                    const uint32_t pa3 = h2u(__floats2half2_rn(s[2*kbk+1][2], s[2*kbk+1][3]));
                    const int vo = hf * 64 + kbk * 16 + 4 * c;
#pragma unroll
                    for (int nb = 0; nb < 8; nb++) {
                        const uint2 vv = *(const uint2*)(SV + (nb * 8 + g) * VSTR + vo);
                        mma_16816_f16(o[nb], pa0, pa1, pa2, pa3, vv.x, vv.y);
                    }
                }
            }
        }
        __syncthreads();
    }

    // ---- finalize ----
    lrow0 += __shfl_xor_sync(0xffffffffu, lrow0, 1);
    lrow0 += __shfl_xor_sync(0xffffffffu, lrow0, 2);
    lrow1 += __shfl_xor_sync(0xffffffffu, lrow1, 1);
    lrow1 += __shfl_xor_sync(0xffffffffu, lrow1, 2);
    const float inv0 = 1.f / lrow0;
    const float inv1 = 1.f / lrow1;

    float* orow0 = out + ((size_t)b * TLEN + r0) * CDIM + h * HD;
    float* orow1 = out + ((size_t)b * TLEN + r1) * CDIM + h * HD;
#pragma unroll
    for (int nb = 0; nb < 8; nb++) {
        const int d = nb * 8 + 2 * c;
        *(float2*)(orow0 + d) = make_float2(o[nb][0] * inv0, o[nb][1] * inv0);
        *(float2*)(orow1 + d) = make_float2(o[nb][2] * inv1, o[nb][3] * inv1);
    }
}

// ---------------------------------------------------------------------------
extern "C" void kernel_launch(void* const* d_in, const int* in_sizes, int n_in,
                              void* d_out, int out_size)
{
    const float* x    = (const float*)d_in[0];
    const float* w    = (const float*)d_in[1];
    const float* bias = (const float*)d_in[2];
    float* out        = (float*)d_out;

    (void)in_sizes; (void)n_in; (void)out_size;

    cudaFuncSetAttribute(qkv_mma_kernel,
                         cudaFuncAttributeMaxDynamicSharedMemorySize, DYN_SMEM);
    cudaFuncSetAttribute(attn_tc_kernel,
                         cudaFuncAttributeMaxDynamicSharedMemorySize, ATTN_SMEM);

    cvt_kernel<<<(NCVT16 + 255) / 256, 256>>>(x, w);

    dim3 ggrid(3 * CDIM / TN, (BSZ * TLEN) / TM);   // (24, 64)
    qkv_mma_kernel<<<ggrid, 256, DYN_SMEM>>>(bias);

    dim3 agrid(TLEN / ATM, BSZ * NHEAD);            // (16, 64)
    attn_tc_kernel<<<agrid, 256, ATTN_SMEM>>>(out);
}

// round 11
// speedup vs baseline: 1.0049x; 1.0049x over previous
#include <cuda_runtime.h>
#include <cuda_fp16.h>
#include <math.h>
#include <stdint.h>

#define BSZ   4
#define TLEN  2048
#define CDIM  1024
#define NHEAD 16
#define HD    64

#define SCRATCH_ELEMS (BSZ * NHEAD * TLEN * HD)   // 8,388,608
#define XN (BSZ * TLEN * CDIM)
#define WN (3 * CDIM * CDIM)

// g_q, g_k: fp16 [bh][t][d'] with d' quad-interleaved within 16-blocks
//           ({2c,2c+1,2c+8,2c+9} -> {4c..4c+3}); Q pre-scaled by 0.125*log2e.
// g_v:      fp16 TRANSPOSED [bh][d][t'] with t' quad-interleaved likewise.
// g_xt/g_wt: x / W as fp16 with k-dim quad-interleaved.
__device__ __half g_q[SCRATCH_ELEMS];
__device__ __half g_k[SCRATCH_ELEMS];
__device__ __half g_v[SCRATCH_ELEMS];
__device__ __half g_xt[XN];
__device__ __half g_wt[WN];

// ===========================================================================
// Helpers
// ===========================================================================
__device__ __forceinline__ uint32_t smem_u32(const void* p) {
    uint32_t a;
    asm("{ .reg .u64 t; cvta.to.shared.u64 t, %1; cvt.u32.u64 %0, t; }"
        : "=r"(a) : "l"(p));
    return a;
}

__device__ __forceinline__ void cp_async16(uint32_t saddr, const void* gaddr) {
    asm volatile("cp.async.cg.shared.global [%0], [%1], 16;"
                 :: "r"(saddr), "l"(gaddr) : "memory");
}
__device__ __forceinline__ void cp_async_commit() {
    asm volatile("cp.async.commit_group;" ::: "memory");
}
template <int N>
__device__ __forceinline__ void cp_async_wait() {
    asm volatile("cp.async.wait_group %0;" :: "n"(N) : "memory");
}

__device__ __forceinline__ float ex2f(float x) {
    float y;
    asm("ex2.approx.ftz.f32 %0, %1;" : "=f"(y) : "f"(x));
    return y;
}

// D(16x8) += A(16x16 row) * B(16x8 col), fp16 in, fp32 accumulate
__device__ __forceinline__ void mma_16816_f16(
    float* d, uint32_t a0, uint32_t a1, uint32_t a2, uint32_t a3,
    uint32_t b0, uint32_t b1)
{
    asm volatile(
        "mma.sync.aligned.m16n8k16.row.col.f32.f16.f16.f32 "
        "{%0,%1,%2,%3}, {%4,%5,%6,%7}, {%8,%9}, {%0,%1,%2,%3};"
        : "+f"(d[0]), "+f"(d[1]), "+f"(d[2]), "+f"(d[3])
        : "r"(a0), "r"(a1), "r"(a2), "r"(a3), "r"(b0), "r"(b1));
}

// quad-interleave within 16-block: k -> 4*((k&7)>>1) + 2*((k>>3)&1) + (k&1)
__device__ __forceinline__ int qperm(int k) {
    return (k & ~15) + 4 * ((k & 7) >> 1) + 2 * ((k >> 3) & 1) + (k & 1);
}

__device__ __forceinline__ uint32_t h2u(half2 h) {
    return *(uint32_t*)&h;
}

// ===========================================================================
// Kernel 0: convert x and W to fp16 with k-quad-interleave  (R9 version)
// ===========================================================================
__global__ void __launch_bounds__(256) cvt_kernel(
    const float* __restrict__ x, const float* __restrict__ w)
{
    const int nx4 = XN / 4;
    const int nw4 = WN / 4;
    const int stride = gridDim.x * blockDim.x;
    for (int i = blockIdx.x * blockDim.x + threadIdx.x; i < nx4 + nw4; i += stride) {
        float4 v;
        __half* dst;
        int base;
        if (i < nx4) { v = ((const float4*)x)[i]; dst = g_xt; base = i * 4; }
        else         { v = ((const float4*)w)[i - nx4]; dst = g_wt; base = (i - nx4) * 4; }
        const int b16 = base & ~15;
        const int o   = base & 15;          // 0,4,8,12
        const float vv[4] = {v.x, v.y, v.z, v.w};
#pragma unroll
        for (int p = 0; p < 2; p++) {
            const int k = o + 2 * p;
            const int d = b16 + 4 * ((k & 7) >> 1) + 2 * ((k >> 3) & 1);
            *(half2*)(dst + d) = __floats2half2_rn(vv[2 * p], vv[2 * p + 1]);
        }
    }
}

// ===========================================================================
// Kernel 1: QKV projection, fp16 m16n8k16. CTA 128x128, warp 32x64, TK=32.
// (R9 version: NSTG=3, wait-then-issue)
// ===========================================================================
#define TM 128
#define TN 128
#define NSTG 3
#define LDH 48                                // halves per row (only 32 used)
#define A_STG_H (TM * LDH)                    // 6144 halves
#define STG_H   (2 * A_STG_H)                 // A + B
#define NCHUNK (CDIM / 32)                    // 32
#define DYN_SMEM (NSTG * STG_H * 2)           // 73728 B
#define Q_PRESCALE (0.125f * 1.44269504f)

__global__ void __launch_bounds__(256, 2) qkv_mma_kernel(
    const float* __restrict__ bias)
{
    extern __shared__ __half smh[];

    const int tid = threadIdx.x;
    const int wid = tid >> 5;
    const int lid = tid & 31;
    const int g   = lid >> 2;
    const int c   = lid & 3;
    const int warp_m = (wid & 3) * 32;
    const int warp_n = (wid >> 2) * 64;
    const int m0  = blockIdx.y * TM;
    const int n0  = blockIdx.x * TN;

    const uint32_t sbase = smem_u32(smh);

    // cp.async mapping: 1024 x 16B chunks per stage, 4 per thread
    const char* gptr[4];
    uint32_t    soff[4];
#pragma unroll
    for (int t = 0; t < 4; t++) {
        const int cc = tid + t * 256;
        if (cc < 512) {
            const int row = cc >> 2, o = cc & 3;
            gptr[t] = (const char*)(g_xt + (size_t)(m0 + row) * CDIM) + o * 16;
            soff[t] = (uint32_t)(row * LDH * 2 + o * 16);
        } else {
            const int cb = cc - 512;
            const int row = cb >> 2, o = cb & 3;
            gptr[t] = (const char*)(g_wt + (size_t)(n0 + row) * CDIM) + o * 16;
            soff[t] = (uint32_t)(A_STG_H * 2 + row * LDH * 2 + o * 16);
        }
    }

#define LOAD_STAGE(chunk)                                                   \
    do {                                                                    \
        const uint32_t sb_ = sbase + ((chunk) % NSTG) * (STG_H * 2);        \
        const int gof_ = (chunk) * 64;   /* 32 halves */                    \
        _Pragma("unroll")                                                   \
        for (int t = 0; t < 4; t++)                                         \
            cp_async16(sb_ + soff[t], gptr[t] + gof_);                      \
        cp_async_commit();                                                  \
    } while (0)

    float acc[2][8][4];
#pragma unroll
    for (int mb = 0; mb < 2; mb++)
#pragma unroll
        for (int nb = 0; nb < 8; nb++)
#pragma unroll
            for (int r = 0; r < 4; r++) acc[mb][nb][r] = 0.f;

    LOAD_STAGE(0);
    LOAD_STAGE(1);

    for (int i = 0; i < NCHUNK; i++) {
        cp_async_wait<NSTG - 2>();
        __syncthreads();

        if (i + 2 < NCHUNK) { LOAD_STAGE(i + 2); }
        else                { cp_async_commit(); }

        const __half* As = smh + (i % NSTG) * STG_H;
        const __half* Bs = As + A_STG_H;

#pragma unroll
        for (int ks = 0; ks < 2; ks++) {        // two k16 steps per 32-chunk
            const int ho = ks * 16 + 4 * c;     // interleaved quad offset
            uint32_t afl[2][2], afh[2][2];
#pragma unroll
            for (int mb = 0; mb < 2; mb++) {
                const uint2 lo = *(const uint2*)(As + (warp_m + mb * 16 + g) * LDH + ho);
                const uint2 hi = *(const uint2*)(As + (warp_m + mb * 16 + g + 8) * LDH + ho);
                afl[mb][0] = lo.x; afl[mb][1] = lo.y;   // a0, a2
                afh[mb][0] = hi.x; afh[mb][1] = hi.y;   // a1, a3
            }
            uint32_t bf[8][2];
#pragma unroll
            for (int nb = 0; nb < 8; nb++) {
                const uint2 bb = *(const uint2*)(Bs + (warp_n + nb * 8 + g) * LDH + ho);
                bf[nb][0] = bb.x; bf[nb][1] = bb.y;
            }
#pragma unroll
            for (int mb = 0; mb < 2; mb++)
#pragma unroll
                for (int nb = 0; nb < 8; nb++)
                    mma_16816_f16(acc[mb][nb],
                                  afl[mb][0], afh[mb][0], afl[mb][1], afh[mb][1],
                                  bf[nb][0], bf[nb][1]);
        }
        __syncthreads();
    }

    // ---- epilogue ----
    const int which = n0 >> 10;                 // 0=Q 1=K 2=V

#pragma unroll
    for (int mb = 0; mb < 2; mb++) {
        const int mA = m0 + warp_m + mb * 16 + g;
        const int mB = mA + 8;
        const int bA = mA >> 11, tA = mA & (TLEN - 1);
        const int bB = mB >> 11, tB = mB & (TLEN - 1);
#pragma unroll
        for (int nb = 0; nb < 8; nb++) {
            const int n = n0 + warp_n + nb * 8 + 2 * c;
            const int h = (n >> 6) & (NHEAD - 1);
            const int d = n & 63;
            const float bx = __ldg(bias + n);
            const float by = __ldg(bias + n + 1);

            if (which == 2) {
                // V^T: [bh][d][t'], t' quad-interleaved
                const int ptA = qperm(tA);
                const int ptB = qperm(tB);
                __half* baseA = g_v + ((size_t)(bA * NHEAD + h) * HD) * TLEN;
                __half* baseB = g_v + ((size_t)(bB * NHEAD + h) * HD) * TLEN;
                baseA[(size_t)d * TLEN + ptA]       = __float2half_rn(acc[mb][nb][0] + bx);
                baseA[(size_t)(d + 1) * TLEN + ptA] = __float2half_rn(acc[mb][nb][1] + by);
                baseB[(size_t)d * TLEN + ptB]       = __float2half_rn(acc[mb][nb][2] + bx);
                baseB[(size_t)(d + 1) * TLEN + ptB] = __float2half_rn(acc[mb][nb][3] + by);
            } else {
                __half* dst = (which == 0) ? g_q : g_k;
                const float sc = (which == 0) ? Q_PRESCALE : 1.0f;
                const int pd = qperm(d);        // d even -> pd, pd+1 adjacent
                __half* pA = dst + (((size_t)(bA * NHEAD + h) * TLEN) + tA) * HD + pd;
                __half* pB = dst + (((size_t)(bB * NHEAD + h) * TLEN) + tB) * HD + pd;
                *(half2*)pA = __floats2half2_rn((acc[mb][nb][0] + bx) * sc,
                                                (acc[mb][nb][1] + by) * sc);
                *(half2*)pB = __floats2half2_rn((acc[mb][nb][2] + bx) * sc,
                                                (acc[mb][nb][3] + by) * sc);
            }
        }
    }
}

// ===========================================================================
// Kernel 2: fp16 TC causal flash attention.
//   CTA = 8 warps = 128 q rows; K/V tiles of 128 keys (two 64-key halves),
//   double-buffered cp.async; Q tile resident in smem. 2 CTAs/SM.
//   Diagonal tile handled by a SEPARATE masked code path (compile-time flag)
//   so non-diagonal tiles run the unpolluted R9 instruction stream.
// ===========================================================================
#define ATM 128
#define ATK 128
#define QSTR 80                        // halves per Q/K row (160 B)
#define KSTR 80
#define VSTR 144                       // halves per V^T row (288 B)
#define QT_H (ATM * QSTR)              // 10240
#define KT_H (ATK * KSTR)              // 10240
#define VT_H (HD * VSTR)               // 9216
#define BUF_H (KT_H + VT_H)            // 19456
#define ATTN_SMEM ((QT_H + 2 * BUF_H) * 2)   // 98304 B

// Process one 64-key half. ISLAST is a literal 0/1: with 0 every guard and
// mask folds away, leaving the clean hot path.
#define PROC_HALF(HF, ISLAST)                                                \
do {                                                                         \
    const int j0h = kt * ATK + (HF) * 64;                                    \
    float s[8][4];                                                           \
    _Pragma("unroll")                                                        \
    for (int nb = 0; nb < 8; nb++) {                                         \
        s[nb][0] = 0.f; s[nb][1] = 0.f; s[nb][2] = 0.f; s[nb][3] = 0.f;      \
    }                                                                        \
    _Pragma("unroll")                                                        \
    for (int ks = 0; ks < 4; ks++) {                                         \
        const int ho = ks * 16 + 4 * c;                                      \
        const uint2 qA = *(const uint2*)(SQ + r0l * QSTR + ho);              \
        const uint2 qB = *(const uint2*)(SQ + (r0l + 8) * QSTR + ho);        \
        _Pragma("unroll")                                                    \
        for (int nb = 0; nb < 8; nb++) {                                     \
            if (!(ISLAST) || (j0h + nb * 8 <= rmax)) {                       \
                const uint2 kk = *(const uint2*)(SK + ((HF) * 64 + nb * 8 + g) * KSTR + ho); \
                mma_16816_f16(s[nb], qA.x, qB.x, qA.y, qB.y, kk.x, kk.y);    \
            }                                                                \
        }                                                                    \
    }                                                                        \
    if (ISLAST) {                                                            \
        _Pragma("unroll")                                                    \
        for (int nb = 0; nb < 8; nb++) {                                     \
            const int jA = j0h + nb * 8 + 2 * c;                             \
            if (jA     > r0) s[nb][0] = -1e30f;                              \
            if (jA + 1 > r0) s[nb][1] = -1e30f;                              \
            if (jA     > r1) s[nb][2] = -1e30f;                              \
            if (jA + 1 > r1) s[nb][3] = -1e30f;                              \
        }                                                                    \
    }                                                                        \
    float t0 = -1e30f, t1 = -1e30f;                                          \
    _Pragma("unroll")                                                        \
    for (int nb = 0; nb < 8; nb++) {                                         \
        t0 = fmaxf(t0, fmaxf(s[nb][0], s[nb][1]));                           \
        t1 = fmaxf(t1, fmaxf(s[nb][2], s[nb][3]));                           \
    }                                                                        \
    t0 = fmaxf(t0, __shfl_xor_sync(0xffffffffu, t0, 1));                     \
    t0 = fmaxf(t0, __shfl_xor_sync(0xffffffffu, t0, 2));                     \
    t1 = fmaxf(t1, __shfl_xor_sync(0xffffffffu, t1, 1));                     \
    t1 = fmaxf(t1, __shfl_xor_sync(0xffffffffu, t1, 2));                     \
    const float mn0 = fmaxf(mrow0, t0);                                      \
    const float mn1 = fmaxf(mrow1, t1);                                      \
    const float a0s = ex2f(mrow0 - mn0);                                     \
    const float a1s = ex2f(mrow1 - mn1);                                     \
    mrow0 = mn0; mrow1 = mn1;                                                \
    lrow0 *= a0s; lrow1 *= a1s;                                              \
    _Pragma("unroll")                                                        \
    for (int nb = 0; nb < 8; nb++) {                                         \
        o[nb][0] *= a0s; o[nb][1] *= a0s;                                    \
        o[nb][2] *= a1s; o[nb][3] *= a1s;                                    \
    }                                                                        \
    _Pragma("unroll")                                                        \
    for (int nb = 0; nb < 8; nb++) {                                         \
        s[nb][0] = ex2f(s[nb][0] - mn0);                                     \
        s[nb][1] = ex2f(s[nb][1] - mn0);                                     \
        s[nb][2] = ex2f(s[nb][2] - mn1);                                     \
        s[nb][3] = ex2f(s[nb][3] - mn1);                                     \
        lrow0 += s[nb][0] + s[nb][1];                                        \
        lrow1 += s[nb][2] + s[nb][3];                                        \
    }                                                                        \
    _Pragma("unroll")                                                        \
    for (int kbk = 0; kbk < 4; kbk++) {                                      \
        if (!(ISLAST) || (j0h + kbk * 16 <= rmax)) {                         \
            const uint32_t pa0 = h2u(__floats2half2_rn(s[2*kbk][0],   s[2*kbk][1]));   \
            const uint32_t pa1 = h2u(__floats2half2_rn(s[2*kbk][2],   s[2*kbk][3]));   \
            const uint32_t pa2 = h2u(__floats2half2_rn(s[2*kbk+1][0], s[2*kbk+1][1])); \
            const uint32_t pa3 = h2u(__floats2half2_rn(s[2*kbk+1][2], s[2*kbk+1][3])); \
            const int vo = (HF) * 64 + kbk * 16 + 4 * c;                     \
            _Pragma("unroll")                                                \
            for (int nb = 0; nb < 8; nb++) {                                 \
                const uint2 vv = *(const uint2*)(SV + (nb * 8 + g) * VSTR + vo); \
                mma_16816_f16(o[nb], pa0, pa1, pa2, pa3, vv.x, vv.y);        \
            }                                                                \
        }                                                                    \
    }                                                                        \
} while (0)

__global__ void __launch_bounds__(256, 2) attn_tc_kernel(float* __restrict__ out)
{
    extern __shared__ __half smh[];
    __half* SQ = smh;
    __half* SB = smh + QT_H;

    const int tid  = threadIdx.x;
    const int wid  = tid >> 5;
    const int lane = tid & 31;
    const int g    = lane >> 2;
    const int c    = lane & 3;
    const int bh   = blockIdx.y;
    const int b    = bh >> 4;
    const int h    = bh & (NHEAD - 1);
    const int q0   = (gridDim.x - 1 - blockIdx.x) * ATM;   // heavy first
    const int r0l  = wid * 16 + g;
    const int r0   = q0 + r0l;
    const int r1   = r0 + 8;
    const int rmax = q0 + wid * 16 + 15;    // warp-uniform max q row

    const __half* qb  = g_q + (size_t)bh * TLEN * HD;
    const __half* kb  = g_k + (size_t)bh * TLEN * HD;
    const __half* vtb = g_v + (size_t)bh * HD * TLEN;

    // ---- Q tile: 128 rows x 128 B (8 chunks/row), 4 chunks/thread ----
    {
        const uint32_t qd = smem_u32(SQ);
#pragma unroll
        for (int i = 0; i < 4; i++) {
            const int id  = tid + i * 256;
            const int row = id >> 3;
            const int o   = id & 7;
            cp_async16(qd + (uint32_t)(row * QSTR * 2 + o * 16),
                       qb + (size_t)(q0 + row) * HD + o * 8);
        }
        cp_async_commit();
    }

    float o[8][4];
#pragma unroll
    for (int nb = 0; nb < 8; nb++)
#pragma unroll
        for (int r = 0; r < 4; r++) o[nb][r] = 0.f;
    float mrow0 = -1e30f, mrow1 = -1e30f;
    float lrow0 = 0.f,    lrow1 = 0.f;

    const int nkt = q0 / ATK + 1;

    // K: 128 keys x 128 B (8 chunks/row); V^T: 64 d x 256 B (16 chunks/row)
#define ATTN_LOAD(kt)                                                        \
    do {                                                                     \
        const int j0_ = (kt) * ATK;                                          \
        const uint32_t sd_ = smem_u32(SB) + ((kt) & 1) * (BUF_H * 2);        \
        _Pragma("unroll")                                                    \
        for (int i_ = 0; i_ < 8; i_++) {                                     \
            const int id_ = tid + i_ * 256;                                  \
            const __half* src_;                                              \
            uint32_t dst_;                                                   \
            if (id_ < 1024) {                                                \
                const int row_ = id_ >> 3, o_ = id_ & 7;                     \
                src_ = kb + (size_t)(j0_ + row_) * HD + o_ * 8;              \
                dst_ = sd_ + (uint32_t)(row_ * KSTR * 2 + o_ * 16);          \
            } else {                                                         \
                const int id2_ = id_ - 1024;                                 \
                const int row_ = id2_ >> 4, o_ = id2_ & 15;                  \
                src_ = vtb + (size_t)row_ * TLEN + j0_ + o_ * 8;             \
                dst_ = sd_ + KT_H * 2                                        \
                     + (uint32_t)(row_ * VSTR * 2 + o_ * 16);                \
            }                                                                \
            cp_async16(dst_, src_);                                          \
        }                                                                    \
        cp_async_commit();                                                   \
    } while (0)

    ATTN_LOAD(0);

    for (int kt = 0; kt < nkt; kt++) {
        if (kt + 1 < nkt) { ATTN_LOAD(kt + 1); cp_async_wait<1>(); }
        else              { cp_async_wait<0>(); }
        __syncthreads();

        const __half* SK = SB + (kt & 1) * BUF_H;
        const __half* SV = SK + KT_H;

        if (kt + 1 < nkt) {
            // clean path: no masking, no guards (folded away at compile time)
            PROC_HALF(0, 0);
            PROC_HALF(1, 0);
        } else {
            // diagonal tile: masked path with exact block skips
            PROC_HALF(0, 1);
            if (kt * ATK + 64 <= rmax) PROC_HALF(1, 1);
        }
        __syncthreads();
    }

    // ---- finalize ----
    lrow0 += __shfl_xor_sync(0xffffffffu, lrow0, 1);
    lrow0 += __shfl_xor_sync(0xffffffffu, lrow0, 2);
    lrow1 += __shfl_xor_sync(0xffffffffu, lrow1, 1);
    lrow1 += __shfl_xor_sync(0xffffffffu, lrow1, 2);
    const float inv0 = 1.f / lrow0;
    const float inv1 = 1.f / lrow1;

    float* orow0 = out + ((size_t)b * TLEN + r0) * CDIM + h * HD;
    float* orow1 = out + ((size_t)b * TLEN + r1) * CDIM + h * HD;
#pragma unroll
    for (int nb = 0; nb < 8; nb++) {
        const int d = nb * 8 + 2 * c;
        *(float2*)(orow0 + d) = make_float2(o[nb][0] * inv0, o[nb][1] * inv0);
        *(float2*)(orow1 + d) = make_float2(o[nb][2] * inv1, o[nb][3] * inv1);
    }
}

// ---------------------------------------------------------------------------
extern "C" void kernel_launch(void* const* d_in, const int* in_sizes, int n_in,
                              void* d_out, int out_size)
{
    const float* x    = (const float*)d_in[0];
    const float* w    = (const float*)d_in[1];
    const float* bias = (const float*)d_in[2];
    float* out        = (float*)d_out;

    (void)in_sizes; (void)n_in; (void)out_size;

    cudaFuncSetAttribute(qkv_mma_kernel,
                         cudaFuncAttributeMaxDynamicSharedMemorySize, DYN_SMEM);
    cudaFuncSetAttribute(attn_tc_kernel,
                         cudaFuncAttributeMaxDynamicSharedMemorySize, ATTN_SMEM);

    cvt_kernel<<<1184, 256>>>(x, w);

    dim3 ggrid(3 * CDIM / TN, (BSZ * TLEN) / TM);   // (24, 64)
    qkv_mma_kernel<<<ggrid, 256, DYN_SMEM>>>(bias);

    dim3 agrid(TLEN / ATM, BSZ * NHEAD);            // (16, 64)
    attn_tc_kernel<<<agrid, 256, ATTN_SMEM>>>(out);
}

// round 13
// speedup vs baseline: 1.0448x; 1.0398x over previous
#include <cuda_runtime.h>
#include <cuda_fp16.h>
#include <math.h>
#include <stdint.h>

#define BSZ   4
#define TLEN  2048
#define CDIM  1024
#define NHEAD 16
#define HD    64

#define SCRATCH_ELEMS (BSZ * NHEAD * TLEN * HD)   // 8,388,608
#define XN (BSZ * TLEN * CDIM)
#define WN (3 * CDIM * CDIM)

// g_q, g_k: fp16 [bh][t][d'] with d' quad-interleaved within 16-blocks
//           ({2c,2c+1,2c+8,2c+9} -> {4c..4c+3}); Q pre-scaled by 0.125*log2e.
// g_v:      fp16 TRANSPOSED [bh][d][t'] with t' quad-interleaved likewise.
// g_xt/g_wt: x / W as fp16 with k-dim quad-interleaved.
__device__ __half g_q[SCRATCH_ELEMS];
__device__ __half g_k[SCRATCH_ELEMS];
__device__ __half g_v[SCRATCH_ELEMS];
__device__ __half g_xt[XN];
__device__ __half g_wt[WN];

// ===========================================================================
// Helpers
// ===========================================================================
__device__ __forceinline__ uint32_t smem_u32(const void* p) {
    uint32_t a;
    asm("{ .reg .u64 t; cvta.to.shared.u64 t, %1; cvt.u32.u64 %0, t; }"
        : "=r"(a) : "l"(p));
    return a;
}

__device__ __forceinline__ void cp_async16(uint32_t saddr, const void* gaddr) {
    asm volatile("cp.async.cg.shared.global [%0], [%1], 16;"
                 :: "r"(saddr), "l"(gaddr) : "memory");
}
__device__ __forceinline__ void cp_async_commit() {
    asm volatile("cp.async.commit_group;" ::: "memory");
}
template <int N>
__device__ __forceinline__ void cp_async_wait() {
    asm volatile("cp.async.wait_group %0;" :: "n"(N) : "memory");
}

__device__ __forceinline__ float ex2f(float x) {
    float y;
    asm("ex2.approx.ftz.f32 %0, %1;" : "=f"(y) : "f"(x));
    return y;
}

// D(16x8) += A(16x16 row) * B(16x8 col), fp16 in, fp32 accumulate
__device__ __forceinline__ void mma_16816_f16(
    float* d, uint32_t a0, uint32_t a1, uint32_t a2, uint32_t a3,
    uint32_t b0, uint32_t b1)
{
    asm volatile(
        "mma.sync.aligned.m16n8k16.row.col.f32.f16.f16.f32 "
        "{%0,%1,%2,%3}, {%4,%5,%6,%7}, {%8,%9}, {%0,%1,%2,%3};"
        : "+f"(d[0]), "+f"(d[1]), "+f"(d[2]), "+f"(d[3])
        : "r"(a0), "r"(a1), "r"(a2), "r"(a3), "r"(b0), "r"(b1));
}

// quad-interleave within 16-block: k -> 4*((k&7)>>1) + 2*((k>>3)&1) + (k&1)
__device__ __forceinline__ int qperm(int k) {
    return (k & ~15) + 4 * ((k & 7) >> 1) + 2 * ((k >> 3) & 1) + (k & 1);
}

__device__ __forceinline__ uint32_t h2u(half2 h) {
    return *(uint32_t*)&h;
}

// ===========================================================================
// Kernel 0: convert x and W to fp16 with k-quad-interleave  (R9 version)
// ===========================================================================
__global__ void __launch_bounds__(256) cvt_kernel(
    const float* __restrict__ x, const float* __restrict__ w)
{
    const int nx4 = XN / 4;
    const int nw4 = WN / 4;
    const int stride = gridDim.x * blockDim.x;
    for (int i = blockIdx.x * blockDim.x + threadIdx.x; i < nx4 + nw4; i += stride) {
        float4 v;
        __half* dst;
        int base;
        if (i < nx4) { v = ((const float4*)x)[i]; dst = g_xt; base = i * 4; }
        else         { v = ((const float4*)w)[i - nx4]; dst = g_wt; base = (i - nx4) * 4; }
        const int b16 = base & ~15;
        const int o   = base & 15;          // 0,4,8,12
        const float vv[4] = {v.x, v.y, v.z, v.w};
#pragma unroll
        for (int p = 0; p < 2; p++) {
            const int k = o + 2 * p;
            const int d = b16 + 4 * ((k & 7) >> 1) + 2 * ((k >> 3) & 1);
            *(half2*)(dst + d) = __floats2half2_rn(vv[2 * p], vv[2 * p + 1]);
        }
    }
}

// ===========================================================================
// Kernel 1: QKV projection, fp16 m16n8k16. CTA 128x128, warp 32x64, TK=32.
// (R9 version: NSTG=3, wait-then-issue)
// ===========================================================================
#define TM 128
#define TN 128
#define NSTG 3
#define LDH 48                                // halves per row (only 32 used)
#define A_STG_H (TM * LDH)                    // 6144 halves
#define STG_H   (2 * A_STG_H)                 // A + B
#define NCHUNK (CDIM / 32)                    // 32
#define DYN_SMEM (NSTG * STG_H * 2)           // 73728 B
#define Q_PRESCALE (0.125f * 1.44269504f)

__global__ void __launch_bounds__(256, 2) qkv_mma_kernel(
    const float* __restrict__ bias)
{
    extern __shared__ __half smh[];

    const int tid = threadIdx.x;
    const int wid = tid >> 5;
    const int lid = tid & 31;
    const int g   = lid >> 2;
    const int c   = lid & 3;
    const int warp_m = (wid & 3) * 32;
    const int warp_n = (wid >> 2) * 64;
    const int m0  = blockIdx.y * TM;
    const int n0  = blockIdx.x * TN;

    const uint32_t sbase = smem_u32(smh);

    // cp.async mapping: 1024 x 16B chunks per stage, 4 per thread
    const char* gptr[4];
    uint32_t    soff[4];
#pragma unroll
    for (int t = 0; t < 4; t++) {
        const int cc = tid + t * 256;
        if (cc < 512) {
            const int row = cc >> 2, o = cc & 3;
            gptr[t] = (const char*)(g_xt + (size_t)(m0 + row) * CDIM) + o * 16;
            soff[t] = (uint32_t)(row * LDH * 2 + o * 16);
        } else {
            const int cb = cc - 512;
            const int row = cb >> 2, o = cb & 3;
            gptr[t] = (const char*)(g_wt + (size_t)(n0 + row) * CDIM) + o * 16;
            soff[t] = (uint32_t)(A_STG_H * 2 + row * LDH * 2 + o * 16);
        }
    }

#define LOAD_STAGE(chunk)                                                   \
    do {                                                                    \
        const uint32_t sb_ = sbase + ((chunk) % NSTG) * (STG_H * 2);        \
        const int gof_ = (chunk) * 64;   /* 32 halves */                    \
        _Pragma("unroll")                                                   \
        for (int t = 0; t < 4; t++)                                         \
            cp_async16(sb_ + soff[t], gptr[t] + gof_);                      \
        cp_async_commit();                                                  \
    } while (0)

    float acc[2][8][4];
#pragma unroll
    for (int mb = 0; mb < 2; mb++)
#pragma unroll
        for (int nb = 0; nb < 8; nb++)
#pragma unroll
            for (int r = 0; r < 4; r++) acc[mb][nb][r] = 0.f;

    LOAD_STAGE(0);
    LOAD_STAGE(1);

    for (int i = 0; i < NCHUNK; i++) {
        cp_async_wait<NSTG - 2>();
        __syncthreads();

        if (i + 2 < NCHUNK) { LOAD_STAGE(i + 2); }
        else                { cp_async_commit(); }

        const __half* As = smh + (i % NSTG) * STG_H;
        const __half* Bs = As + A_STG_H;

#pragma unroll
        for (int ks = 0; ks < 2; ks++) {        // two k16 steps per 32-chunk
            const int ho = ks * 16 + 4 * c;     // interleaved quad offset
            uint32_t afl[2][2], afh[2][2];
#pragma unroll
            for (int mb = 0; mb < 2; mb++) {
                const uint2 lo = *(const uint2*)(As + (warp_m + mb * 16 + g) * LDH + ho);
                const uint2 hi = *(const uint2*)(As + (warp_m + mb * 16 + g + 8) * LDH + ho);
                afl[mb][0] = lo.x; afl[mb][1] = lo.y;   // a0, a2
                afh[mb][0] = hi.x; afh[mb][1] = hi.y;   // a1, a3
            }
            uint32_t bf[8][2];
#pragma unroll
            for (int nb = 0; nb < 8; nb++) {
                const uint2 bb = *(const uint2*)(Bs + (warp_n + nb * 8 + g) * LDH + ho);
                bf[nb][0] = bb.x; bf[nb][1] = bb.y;
            }
#pragma unroll
            for (int mb = 0; mb < 2; mb++)
#pragma unroll
                for (int nb = 0; nb < 8; nb++)
                    mma_16816_f16(acc[mb][nb],
                                  afl[mb][0], afh[mb][0], afl[mb][1], afh[mb][1],
                                  bf[nb][0], bf[nb][1]);
        }
        __syncthreads();
    }

    // ---- epilogue ----
    const int which = n0 >> 10;                 // 0=Q 1=K 2=V

#pragma unroll
    for (int mb = 0; mb < 2; mb++) {
        const int mA = m0 + warp_m + mb * 16 + g;
        const int mB = mA + 8;
        const int bA = mA >> 11, tA = mA & (TLEN - 1);
        const int bB = mB >> 11, tB = mB & (TLEN - 1);
#pragma unroll
        for (int nb = 0; nb < 8; nb++) {
            const int n = n0 + warp_n + nb * 8 + 2 * c;
            const int h = (n >> 6) & (NHEAD - 1);
            const int d = n & 63;
            const float bx = __ldg(bias + n);
            const float by = __ldg(bias + n + 1);

            if (which == 2) {
                // V^T: [bh][d][t'], t' quad-interleaved
                const int ptA = qperm(tA);
                const int ptB = qperm(tB);
                __half* baseA = g_v + ((size_t)(bA * NHEAD + h) * HD) * TLEN;
                __half* baseB = g_v + ((size_t)(bB * NHEAD + h) * HD) * TLEN;
                baseA[(size_t)d * TLEN + ptA]       = __float2half_rn(acc[mb][nb][0] + bx);
                baseA[(size_t)(d + 1) * TLEN + ptA] = __float2half_rn(acc[mb][nb][1] + by);
                baseB[(size_t)d * TLEN + ptB]       = __float2half_rn(acc[mb][nb][2] + bx);
                baseB[(size_t)(d + 1) * TLEN + ptB] = __float2half_rn(acc[mb][nb][3] + by);
            } else {
                __half* dst = (which == 0) ? g_q : g_k;
                const float sc = (which == 0) ? Q_PRESCALE : 1.0f;
                const int pd = qperm(d);        // d even -> pd, pd+1 adjacent
                __half* pA = dst + (((size_t)(bA * NHEAD + h) * TLEN) + tA) * HD + pd;
                __half* pB = dst + (((size_t)(bB * NHEAD + h) * TLEN) + tB) * HD + pd;
                *(half2*)pA = __floats2half2_rn((acc[mb][nb][0] + bx) * sc,
                                                (acc[mb][nb][1] + by) * sc);
                *(half2*)pB = __floats2half2_rn((acc[mb][nb][2] + bx) * sc,
                                                (acc[mb][nb][3] + by) * sc);
            }
        }
    }
}

// ===========================================================================
// Kernel 2: fp16 TC causal flash attention (R9 structure; Q fragments in
// registers, loaded once from gmem — SQ smem tile deleted).
//   CTA = 8 warps = 128 q rows; K/V tiles of 128 keys (two 64-key halves),
//   double-buffered cp.async. 2 CTAs/SM.
// ===========================================================================
#define ATM 128
#define ATK 128
#define KSTR 80                        // halves per K row (160 B)
#define VSTR 144                       // halves per V^T row (288 B)
#define KT_H (ATK * KSTR)              // 10240
#define VT_H (HD * VSTR)               // 9216
#define BUF_H (KT_H + VT_H)            // 19456
#define ATTN_SMEM (2 * BUF_H * 2)      // 77824 B

__global__ void __launch_bounds__(256, 2) attn_tc_kernel(float* __restrict__ out)
{
    extern __shared__ __half smh[];
    __half* SB = smh;

    const int tid  = threadIdx.x;
    const int wid  = tid >> 5;
    const int lane = tid & 31;
    const int g    = lane >> 2;
    const int c    = lane & 3;
    const int bh   = blockIdx.y;
    const int b    = bh >> 4;
    const int h    = bh & (NHEAD - 1);
    const int q0   = (gridDim.x - 1 - blockIdx.x) * ATM;   // heavy first
    const int r0l  = wid * 16 + g;
    const int r0   = q0 + r0l;
    const int r1   = r0 + 8;

    const __half* qb  = g_q + (size_t)bh * TLEN * HD;
    const __half* kb  = g_k + (size_t)bh * TLEN * HD;
    const __half* vtb = g_v + (size_t)bh * HD * TLEN;

    const int nkt = q0 / ATK + 1;

    // K: 128 keys x 128 B (8 chunks/row); V^T: 64 d x 256 B (16 chunks/row)
#define ATTN_LOAD(kt)                                                        \
    do {                                                                     \
        const int j0_ = (kt) * ATK;                                          \
        const uint32_t sd_ = smem_u32(SB) + ((kt) & 1) * (BUF_H * 2);        \
        _Pragma("unroll")                                                    \
        for (int i_ = 0; i_ < 8; i_++) {                                     \
            const int id_ = tid + i_ * 256;                                  \
            const __half* src_;                                              \
            uint32_t dst_;                                                   \
            if (id_ < 1024) {                                                \
                const int row_ = id_ >> 3, o_ = id_ & 7;                     \
                src_ = kb + (size_t)(j0_ + row_) * HD + o_ * 8;              \
                dst_ = sd_ + (uint32_t)(row_ * KSTR * 2 + o_ * 16);          \
            } else {                                                         \
                const int id2_ = id_ - 1024;                                 \
                const int row_ = id2_ >> 4, o_ = id2_ & 15;                  \
                src_ = vtb + (size_t)row_ * TLEN + j0_ + o_ * 8;             \
                dst_ = sd_ + KT_H * 2                                        \
                     + (uint32_t)(row_ * VSTR * 2 + o_ * 16);                \
            }                                                                \
            cp_async16(dst_, src_);                                          \
        }                                                                    \
        cp_async_commit();                                                   \
    } while (0)

    ATTN_LOAD(0);

    // ---- Q fragments: loaded ONCE from gmem into registers (16 uint2).
    // Same interleaved addresses the former smem tile held; LDG latency is
    // covered by the ATTN_LOAD(0) wait below.
    uint2 qf0[4], qf1[4];
#pragma unroll
    for (int ks = 0; ks < 4; ks++) {
        const int ho = ks * 16 + 4 * c;
        qf0[ks] = *(const uint2*)(qb + (size_t)r0 * HD + ho);
        qf1[ks] = *(const uint2*)(qb + (size_t)r1 * HD + ho);
    }

    float o[8][4];
#pragma unroll
    for (int nb = 0; nb < 8; nb++)
#pragma unroll
        for (int r = 0; r < 4; r++) o[nb][r] = 0.f;
    float mrow0 = -1e30f, mrow1 = -1e30f;
    float lrow0 = 0.f,    lrow1 = 0.f;

    for (int kt = 0; kt < nkt; kt++) {
        if (kt + 1 < nkt) { ATTN_LOAD(kt + 1); cp_async_wait<1>(); }
        else              { cp_async_wait<0>(); }
        __syncthreads();

        const __half* SK = SB + (kt & 1) * BUF_H;
        const __half* SV = SK + KT_H;
        const bool last = (kt == nkt - 1);

#pragma unroll
        for (int hf = 0; hf < 2; hf++) {
            const int j0h = kt * ATK + hf * 64;
            if (j0h > q0 + wid * 16 + 15) break;   // warp fully masked

            // ---- S = Q K^T (16 x 64) ----
            float s[8][4];
#pragma unroll
            for (int nb = 0; nb < 8; nb++)
#pragma unroll
                for (int r = 0; r < 4; r++) s[nb][r] = 0.f;

#pragma unroll
            for (int ks = 0; ks < 4; ks++) {
                const int ho = ks * 16 + 4 * c;
#pragma unroll
                for (int nb = 0; nb < 8; nb++) {
                    const uint2 kk = *(const uint2*)(SK + (hf * 64 + nb * 8 + g) * KSTR + ho);
                    mma_16816_f16(s[nb], qf0[ks].x, qf1[ks].x, qf0[ks].y, qf1[ks].y,
                                  kk.x, kk.y);
                }
            }

            // ---- causal mask (last tile only) ----
            if (last) {
#pragma unroll
                for (int nb = 0; nb < 8; nb++) {
                    const int jA = j0h + nb * 8 + 2 * c;
                    if (jA     > r0) s[nb][0] = -1e30f;
                    if (jA + 1 > r0) s[nb][1] = -1e30f;
                    if (jA     > r1) s[nb][2] = -1e30f;
                    if (jA + 1 > r1) s[nb][3] = -1e30f;
                }
            }

            // ---- online softmax (base 2) ----
            float t0 = -1e30f, t1 = -1e30f;
#pragma unroll
            for (int nb = 0; nb < 8; nb++) {
                t0 = fmaxf(t0, fmaxf(s[nb][0], s[nb][1]));
                t1 = fmaxf(t1, fmaxf(s[nb][2], s[nb][3]));
            }
            t0 = fmaxf(t0, __shfl_xor_sync(0xffffffffu, t0, 1));
            t0 = fmaxf(t0, __shfl_xor_sync(0xffffffffu, t0, 2));
            t1 = fmaxf(t1, __shfl_xor_sync(0xffffffffu, t1, 1));
            t1 = fmaxf(t1, __shfl_xor_sync(0xffffffffu, t1, 2));

            const float mn0 = fmaxf(mrow0, t0);
            const float mn1 = fmaxf(mrow1, t1);
            const float a0s = ex2f(mrow0 - mn0);
            const float a1s = ex2f(mrow1 - mn1);
            mrow0 = mn0; mrow1 = mn1;
            lrow0 *= a0s; lrow1 *= a1s;
#pragma unroll
            for (int nb = 0; nb < 8; nb++) {
                o[nb][0] *= a0s; o[nb][1] *= a0s;
                o[nb][2] *= a1s; o[nb][3] *= a1s;
            }

#pragma unroll
            for (int nb = 0; nb < 8; nb++) {
                s[nb][0] = ex2f(s[nb][0] - mn0);
                s[nb][1] = ex2f(s[nb][1] - mn0);
                s[nb][2] = ex2f(s[nb][2] - mn1);
                s[nb][3] = ex2f(s[nb][3] - mn1);
                lrow0 += s[nb][0] + s[nb][1];
                lrow1 += s[nb][2] + s[nb][3];
            }

            // ---- O += P V:  P(16x64) packed from S, V^T key-interleaved ----
#pragma unroll
            for (int kbk = 0; kbk < 4; kbk++) {     // 4 k16 blocks of keys
                const uint32_t pa0 = h2u(__floats2half2_rn(s[2*kbk][0],   s[2*kbk][1]));
                const uint32_t pa1 = h2u(__floats2half2_rn(s[2*kbk][2],   s[2*kbk][3]));
                const uint32_t pa2 = h2u(__floats2half2_rn(s[2*kbk+1][0], s[2*kbk+1][1]));
                const uint32_t pa3 = h2u(__floats2half2_rn(s[2*kbk+1][2], s[2*kbk+1][3]));
                const int vo = hf * 64 + kbk * 16 + 4 * c;
#pragma unroll
                for (int nb = 0; nb < 8; nb++) {
                    const uint2 vv = *(const uint2*)(SV + (nb * 8 + g) * VSTR + vo);
                    mma_16816_f16(o[nb], pa0, pa1, pa2, pa3, vv.x, vv.y);
                }
            }
        }
        __syncthreads();
    }

    // ---- finalize ----
    lrow0 += __shfl_xor_sync(0xffffffffu, lrow0, 1);
    lrow0 += __shfl_xor_sync(0xffffffffu, lrow0, 2);
    lrow1 += __shfl_xor_sync(0xffffffffu, lrow1, 1);
    lrow1 += __shfl_xor_sync(0xffffffffu, lrow1, 2);
    const float inv0 = 1.f / lrow0;
    const float inv1 = 1.f / lrow1;

    float* orow0 = out + ((size_t)b * TLEN + r0) * CDIM + h * HD;
    float* orow1 = out + ((size_t)b * TLEN + r1) * CDIM + h * HD;
#pragma unroll
    for (int nb = 0; nb < 8; nb++) {
        const int d = nb * 8 + 2 * c;
        *(float2*)(orow0 + d) = make_float2(o[nb][0] * inv0, o[nb][1] * inv0);
        *(float2*)(orow1 + d) = make_float2(o[nb][2] * inv1, o[nb][3] * inv1);
    }
}

// ---------------------------------------------------------------------------
extern "C" void kernel_launch(void* const* d_in, const int* in_sizes, int n_in,
                              void* d_out, int out_size)
{
    const float* x    = (const float*)d_in[0];
    const float* w    = (const float*)d_in[1];
    const float* bias = (const float*)d_in[2];
    float* out        = (float*)d_out;

    (void)in_sizes; (void)n_in; (void)out_size;

    cudaFuncSetAttribute(qkv_mma_kernel,
                         cudaFuncAttributeMaxDynamicSharedMemorySize, DYN_SMEM);
    cudaFuncSetAttribute(attn_tc_kernel,
                         cudaFuncAttributeMaxDynamicSharedMemorySize, ATTN_SMEM);

    cvt_kernel<<<1184, 256>>>(x, w);

    dim3 ggrid(3 * CDIM / TN, (BSZ * TLEN) / TM);   // (24, 64)
    qkv_mma_kernel<<<ggrid, 256, DYN_SMEM>>>(bias);

    dim3 agrid(TLEN / ATM, BSZ * NHEAD);            // (16, 64)
    attn_tc_kernel<<<agrid, 256, ATTN_SMEM>>>(out);
}

// round 15
// speedup vs baseline: 1.0515x; 1.0064x over previous
#include <cuda_runtime.h>
#include <cuda_fp16.h>
#include <math.h>
#include <stdint.h>

#define BSZ   4
#define TLEN  2048
#define CDIM  1024
#define NHEAD 16
#define HD    64

#define SCRATCH_ELEMS (BSZ * NHEAD * TLEN * HD)   // 8,388,608
#define WN (3 * CDIM * CDIM)

// g_q, g_k: fp16 [bh][t][d'] with d' quad-interleaved within 16-blocks
//           ({2c,2c+1,2c+8,2c+9} -> {4c..4c+3}); Q pre-scaled by 0.125*log2e.
// g_v:      fp16 TRANSPOSED [bh][d][t'] with t' quad-interleaved likewise.
// g_wt:     W as fp16 with k-dim quad-interleaved. (x stays fp32 — converted
//           in-register inside the GEMM A-path.)
__device__ __half g_q[SCRATCH_ELEMS];
__device__ __half g_k[SCRATCH_ELEMS];
__device__ __half g_v[SCRATCH_ELEMS];
__device__ __half g_wt[WN];

// ===========================================================================
// Helpers
// ===========================================================================
__device__ __forceinline__ uint32_t smem_u32(const void* p) {
    uint32_t a;
    asm("{ .reg .u64 t; cvta.to.shared.u64 t, %1; cvt.u32.u64 %0, t; }"
        : "=r"(a) : "l"(p));
    return a;
}

__device__ __forceinline__ void cp_async16(uint32_t saddr, const void* gaddr) {
    asm volatile("cp.async.cg.shared.global [%0], [%1], 16;"
                 :: "r"(saddr), "l"(gaddr) : "memory");
}
__device__ __forceinline__ void cp_async_commit() {
    asm volatile("cp.async.commit_group;" ::: "memory");
}
template <int N>
__device__ __forceinline__ void cp_async_wait() {
    asm volatile("cp.async.wait_group %0;" :: "n"(N) : "memory");
}

__device__ __forceinline__ float ex2f(float x) {
    float y;
    asm("ex2.approx.ftz.f32 %0, %1;" : "=f"(y) : "f"(x));
    return y;
}

// D(16x8) += A(16x16 row) * B(16x8 col), fp16 in, fp32 accumulate
__device__ __forceinline__ void mma_16816_f16(
    float* d, uint32_t a0, uint32_t a1, uint32_t a2, uint32_t a3,
    uint32_t b0, uint32_t b1)
{
    asm volatile(
        "mma.sync.aligned.m16n8k16.row.col.f32.f16.f16.f32 "
        "{%0,%1,%2,%3}, {%4,%5,%6,%7}, {%8,%9}, {%0,%1,%2,%3};"
        : "+f"(d[0]), "+f"(d[1]), "+f"(d[2]), "+f"(d[3])
        : "r"(a0), "r"(a1), "r"(a2), "r"(a3), "r"(b0), "r"(b1));
}

// quad-interleave within 16-block: k -> 4*((k&7)>>1) + 2*((k>>3)&1) + (k&1)
__device__ __forceinline__ int qperm(int k) {
    return (k & ~15) + 4 * ((k & 7) >> 1) + 2 * ((k >> 3) & 1) + (k & 1);
}

__device__ __forceinline__ uint32_t h2u(half2 h) {
    return *(uint32_t*)&h;
}

// ===========================================================================
// Kernel 0: convert W (only) to fp16 with k-quad-interleave
// ===========================================================================
__global__ void __launch_bounds__(256) cvt_kernel(const float* __restrict__ w)
{
    const int nw4 = WN / 4;
    const int stride = gridDim.x * blockDim.x;
    for (int i = blockIdx.x * blockDim.x + threadIdx.x; i < nw4; i += stride) {
        const float4 v = ((const float4*)w)[i];
        const int base = i * 4;
        const int b16 = base & ~15;
        const int o   = base & 15;          // 0,4,8,12
        const float vv[4] = {v.x, v.y, v.z, v.w};
#pragma unroll
        for (int p = 0; p < 2; p++) {
            const int k = o + 2 * p;
            const int d = b16 + 4 * ((k & 7) >> 1) + 2 * ((k >> 3) & 1);
            *(half2*)(g_wt + d) = __floats2half2_rn(vv[2 * p], vv[2 * p + 1]);
        }
    }
}

// ===========================================================================
// Kernel 1: QKV projection, fp16 m16n8k16. CTA 128x128, warp 32x64, TK=32.
//   A (x) staged as RAW FP32 (stride 40 floats, conflict-free), converted to
//   fp16 fragments in-register; B (W) staged as pre-interleaved fp16.
//   NSTG=3; single __syncthreads per chunk (trailing sync proven redundant).
// ===========================================================================
#define TM 128
#define TN 128
#define NSTG 3
#define LDPF 40                               // floats per A row (160 B)
#define LDH 48                                // halves per B row (only 32 used)
#define A_STG_B (TM * LDPF * 4)               // 20480 B
#define B_STG_B (TN * LDH * 2)                // 12288 B
#define STG_B   (A_STG_B + B_STG_B)           // 32768 B
#define NCHUNK (CDIM / 32)                    // 32
#define DYN_SMEM (NSTG * STG_B)               // 98304 B
#define Q_PRESCALE (0.125f * 1.44269504f)

__global__ void __launch_bounds__(256, 2) qkv_mma_kernel(
    const float* __restrict__ x,
    const float* __restrict__ bias)
{
    extern __shared__ char smc[];

    const int tid = threadIdx.x;
    const int wid = tid >> 5;
    const int lid = tid & 31;
    const int g   = lid >> 2;
    const int c   = lid & 3;
    const int warp_m = (wid & 3) * 32;
    const int warp_n = (wid >> 2) * 64;
    const int m0  = blockIdx.y * TM;
    const int n0  = blockIdx.x * TN;

    const uint32_t sbase = smem_u32(smc);

    // cp.async mapping: 1536 x 16B chunks per stage, 6 per thread.
    // ids 0..1023 -> A fp32 (128 rows x 8 chunks, 128 B of x per chunk-col),
    // ids 1024..1535 -> B fp16 (128 rows x 4 chunks).
    const char* gptr[6];
    uint32_t    soff[6];
    int         gstep[6];
#pragma unroll
    for (int t = 0; t < 6; t++) {
        const int cc = tid + t * 256;
        if (cc < 1024) {
            const int row = cc >> 3, o = cc & 7;
            gptr[t]  = (const char*)(x + (size_t)(m0 + row) * CDIM) + o * 16;
            soff[t]  = (uint32_t)(row * LDPF * 4 + o * 16);
            gstep[t] = 128;                    // 32 floats per chunk
        } else {
            const int cb = cc - 1024;
            const int row = cb >> 2, o = cb & 3;
            gptr[t]  = (const char*)(g_wt + (size_t)(n0 + row) * CDIM) + o * 16;
            soff[t]  = (uint32_t)(A_STG_B + row * LDH * 2 + o * 16);
            gstep[t] = 64;                     // 32 halves per chunk
        }
    }

#define LOAD_STAGE(chunk)                                                   \
    do {                                                                    \
        const uint32_t sb_ = sbase + ((chunk) % NSTG) * STG_B;              \
        _Pragma("unroll")                                                   \
        for (int t = 0; t < 6; t++)                                         \
            cp_async16(sb_ + soff[t], gptr[t] + (chunk) * gstep[t]);        \
        cp_async_commit();                                                  \
    } while (0)

    float acc[2][8][4];
#pragma unroll
    for (int mb = 0; mb < 2; mb++)
#pragma unroll
        for (int nb = 0; nb < 8; nb++)
#pragma unroll
            for (int r = 0; r < 4; r++) acc[mb][nb][r] = 0.f;

    LOAD_STAGE(0);
    LOAD_STAGE(1);

    for (int i = 0; i < NCHUNK; i++) {
        cp_async_wait<NSTG - 2>();
        __syncthreads();     // orders: chunk i visible AND compute(i-1) done
                             // before load(i+2) overwrites buffer (i-1)%3

        if (i + 2 < NCHUNK) { LOAD_STAGE(i + 2); }
        else                { cp_async_commit(); }

        const float*  Af = (const float*)(smc + (i % NSTG) * STG_B);
        const __half* Bs = (const __half*)(smc + (i % NSTG) * STG_B + A_STG_B);

#pragma unroll
        for (int ks = 0; ks < 2; ks++) {        // two k16 steps per 32-chunk
            // A fragments: fp32 -> fp16 packed in-register
            uint32_t af[2][4];                  // [mb][a0,a1,a2,a3]
#pragma unroll
            for (int mb = 0; mb < 2; mb++) {
                const float* rlo = Af + (warp_m + mb * 16 + g)     * LDPF + ks * 16 + 2 * c;
                const float* rhi = Af + (warp_m + mb * 16 + g + 8) * LDPF + ks * 16 + 2 * c;
                const float2 lo0 = *(const float2*)(rlo);
                const float2 lo1 = *(const float2*)(rlo + 8);
                const float2 hi0 = *(const float2*)(rhi);
                const float2 hi1 = *(const float2*)(rhi + 8);
                af[mb][0] = h2u(__floats2half2_rn(lo0.x, lo0.y));   // a0: k 2c,2c+1
                af[mb][1] = h2u(__floats2half2_rn(hi0.x, hi0.y));   // a1
                af[mb][2] = h2u(__floats2half2_rn(lo1.x, lo1.y));   // a2: k 2c+8,2c+9
                af[mb][3] = h2u(__floats2half2_rn(hi1.x, hi1.y));   // a3
            }
            // B fragments: pre-interleaved fp16, 1 LDS.64 each
            const int ho = ks * 16 + 4 * c;
            uint32_t bf[8][2];
#pragma unroll
            for (int nb = 0; nb < 8; nb++) {
                const uint2 bb = *(const uint2*)(Bs + (warp_n + nb * 8 + g) * LDH + ho);
                bf[nb][0] = bb.x; bf[nb][1] = bb.y;
            }
#pragma unroll
            for (int mb = 0; mb < 2; mb++)
#pragma unroll
                for (int nb = 0; nb < 8; nb++)
                    mma_16816_f16(acc[mb][nb],
                                  af[mb][0], af[mb][1], af[mb][2], af[mb][3],
                                  bf[nb][0], bf[nb][1]);
        }
        // (trailing __syncthreads removed — next iteration's top sync covers it)
    }

    // ---- epilogue ----
    const int which = n0 >> 10;                 // 0=Q 1=K 2=V

#pragma unroll
    for (int mb = 0; mb < 2; mb++) {
        const int mA = m0 + warp_m + mb * 16 + g;
        const int mB = mA + 8;
        const int bA = mA >> 11, tA = mA & (TLEN - 1);
        const int bB = mB >> 11, tB = mB & (TLEN - 1);
#pragma unroll
        for (int nb = 0; nb < 8; nb++) {
            const int n = n0 + warp_n + nb * 8 + 2 * c;
            const int h = (n >> 6) & (NHEAD - 1);
            const int d = n & 63;
            const float bx = __ldg(bias + n);
            const float by = __ldg(bias + n + 1);

            if (which == 2) {
                // V^T: [bh][d][t'], t' quad-interleaved
                const int ptA = qperm(tA);
                const int ptB = qperm(tB);
                __half* baseA = g_v + ((size_t)(bA * NHEAD + h) * HD) * TLEN;
                __half* baseB = g_v + ((size_t)(bB * NHEAD + h) * HD) * TLEN;
                baseA[(size_t)d * TLEN + ptA]       = __float2half_rn(acc[mb][nb][0] + bx);
                baseA[(size_t)(d + 1) * TLEN + ptA] = __float2half_rn(acc[mb][nb][1] + by);
                baseB[(size_t)d * TLEN + ptB]       = __float2half_rn(acc[mb][nb][2] + bx);
                baseB[(size_t)(d + 1) * TLEN + ptB] = __float2half_rn(acc[mb][nb][3] + by);
            } else {
                __half* dst = (which == 0) ? g_q : g_k;
                const float sc = (which == 0) ? Q_PRESCALE : 1.0f;
                const int pd = qperm(d);        // d even -> pd, pd+1 adjacent
                __half* pA = dst + (((size_t)(bA * NHEAD + h) * TLEN) + tA) * HD + pd;
                __half* pB = dst + (((size_t)(bB * NHEAD + h) * TLEN) + tB) * HD + pd;
                *(half2*)pA = __floats2half2_rn((acc[mb][nb][0] + bx) * sc,
                                                (acc[mb][nb][1] + by) * sc);
                *(half2*)pB = __floats2half2_rn((acc[mb][nb][2] + bx) * sc,
                                                (acc[mb][nb][3] + by) * sc);
            }
        }
    }
}

// ===========================================================================
// Kernel 2: fp16 TC causal flash attention (exact R13 — current best).
//   CTA = 8 warps = 128 q rows; K/V tiles of 128 keys (two 64-key halves),
//   double-buffered cp.async; Q fragments in registers. 2 CTAs/SM.
// ===========================================================================
#define ATM 128
#define ATK 128
#define KSTR 80                        // halves per K row (160 B)
#define VSTR 144                       // halves per V^T row (288 B)
#define KT_H (ATK * KSTR)              // 10240
#define VT_H (HD * VSTR)               // 9216
#define BUF_H (KT_H + VT_H)            // 19456
#define ATTN_SMEM (2 * BUF_H * 2)      // 77824 B

__global__ void __launch_bounds__(256, 2) attn_tc_kernel(float* __restrict__ out)
{
    extern __shared__ __half smh[];
    __half* SB = smh;

    const int tid  = threadIdx.x;
    const int wid  = tid >> 5;
    const int lane = tid & 31;
    const int g    = lane >> 2;
    const int c    = lane & 3;
    const int bh   = blockIdx.y;
    const int b    = bh >> 4;
    const int h    = bh & (NHEAD - 1);
    const int q0   = (gridDim.x - 1 - blockIdx.x) * ATM;   // heavy first
    const int r0l  = wid * 16 + g;
    const int r0   = q0 + r0l;
    const int r1   = r0 + 8;

    const __half* qb  = g_q + (size_t)bh * TLEN * HD;
    const __half* kb  = g_k + (size_t)bh * TLEN * HD;
    const __half* vtb = g_v + (size_t)bh * HD * TLEN;

    const int nkt = q0 / ATK + 1;

    // K: 128 keys x 128 B (8 chunks/row); V^T: 64 d x 256 B (16 chunks/row)
#define ATTN_LOAD(kt)                                                        \
    do {                                                                     \
        const int j0_ = (kt) * ATK;                                          \
        const uint32_t sd_ = smem_u32(SB) + ((kt) & 1) * (BUF_H * 2);        \
        _Pragma("unroll")                                                    \
        for (int i_ = 0; i_ < 8; i_++) {                                     \
            const int id_ = tid + i_ * 256;                                  \
            const __half* src_;                                              \
            uint32_t dst_;                                                   \
            if (id_ < 1024) {                                                \
                const int row_ = id_ >> 3, o_ = id_ & 7;                     \
                src_ = kb + (size_t)(j0_ + row_) * HD + o_ * 8;              \
                dst_ = sd_ + (uint32_t)(row_ * KSTR * 2 + o_ * 16);          \
            } else {                                                         \
                const int id2_ = id_ - 1024;                                 \
                const int row_ = id2_ >> 4, o_ = id2_ & 15;                  \
                src_ = vtb + (size_t)row_ * TLEN + j0_ + o_ * 8;             \
                dst_ = sd_ + KT_H * 2                                        \
                     + (uint32_t)(row_ * VSTR * 2 + o_ * 16);                \
            }                                                                \
            cp_async16(dst_, src_);                                          \
        }                                                                    \
        cp_async_commit();                                                   \
    } while (0)

    ATTN_LOAD(0);

    // ---- Q fragments: loaded ONCE from gmem into registers (16 uint2).
    uint2 qf0[4], qf1[4];
#pragma unroll
    for (int ks = 0; ks < 4; ks++) {
        const int ho = ks * 16 + 4 * c;
        qf0[ks] = *(const uint2*)(qb + (size_t)r0 * HD + ho);
        qf1[ks] = *(const uint2*)(qb + (size_t)r1 * HD + ho);
    }

    float o[8][4];
#pragma unroll
    for (int nb = 0; nb < 8; nb++)
#pragma unroll
        for (int r = 0; r < 4; r++) o[nb][r] = 0.f;
    float mrow0 = -1e30f, mrow1 = -1e30f;
    float lrow0 = 0.f,    lrow1 = 0.f;

    for (int kt = 0; kt < nkt; kt++) {
        if (kt + 1 < nkt) { ATTN_LOAD(kt + 1); cp_async_wait<1>(); }
        else              { cp_async_wait<0>(); }
        __syncthreads();

        const __half* SK = SB + (kt & 1) * BUF_H;
        const __half* SV = SK + KT_H;
        const bool last = (kt == nkt - 1);

#pragma unroll
        for (int hf = 0; hf < 2; hf++) {
            const int j0h = kt * ATK + hf * 64;
            if (j0h > q0 + wid * 16 + 15) break;   // warp fully masked

            // ---- S = Q K^T (16 x 64) ----
            float s[8][4];
#pragma unroll
            for (int nb = 0; nb < 8; nb++)
#pragma unroll
                for (int r = 0; r < 4; r++) s[nb][r] = 0.f;

#pragma unroll
            for (int ks = 0; ks < 4; ks++) {
                const int ho = ks * 16 + 4 * c;
#pragma unroll
                for (int nb = 0; nb < 8; nb++) {
                    const uint2 kk = *(const uint2*)(SK + (hf * 64 + nb * 8 + g) * KSTR + ho);
                    mma_16816_f16(s[nb], qf0[ks].x, qf1[ks].x, qf0[ks].y, qf1[ks].y,
                                  kk.x, kk.y);
                }
            }

            // ---- causal mask (last tile only) ----
            if (last) {
#pragma unroll
                for (int nb = 0; nb < 8; nb++) {
                    const int jA = j0h + nb * 8 + 2 * c;
                    if (jA     > r0) s[nb][0] = -1e30f;
                    if (jA + 1 > r0) s[nb][1] = -1e30f;
                    if (jA     > r1) s[nb][2] = -1e30f;
                    if (jA + 1 > r1) s[nb][3] = -1e30f;
                }
            }

            // ---- online softmax (base 2) ----
            float t0 = -1e30f, t1 = -1e30f;
#pragma unroll
            for (int nb = 0; nb < 8; nb++) {
                t0 = fmaxf(t0, fmaxf(s[nb][0], s[nb][1]));
                t1 = fmaxf(t1, fmaxf(s[nb][2], s[nb][3]));
            }
            t0 = fmaxf(t0, __shfl_xor_sync(0xffffffffu, t0, 1));
            t0 = fmaxf(t0, __shfl_xor_sync(0xffffffffu, t0, 2));
            t1 = fmaxf(t1, __shfl_xor_sync(0xffffffffu, t1, 1));
            t1 = fmaxf(t1, __shfl_xor_sync(0xffffffffu, t1, 2));

            const float mn0 = fmaxf(mrow0, t0);
            const float mn1 = fmaxf(mrow1, t1);
            const float a0s = ex2f(mrow0 - mn0);
            const float a1s = ex2f(mrow1 - mn1);
            mrow0 = mn0; mrow1 = mn1;
            lrow0 *= a0s; lrow1 *= a1s;
#pragma unroll
            for (int nb = 0; nb < 8; nb++) {
                o[nb][0] *= a0s; o[nb][1] *= a0s;
                o[nb][2] *= a1s; o[nb][3] *= a1s;
            }

#pragma unroll
            for (int nb = 0; nb < 8; nb++) {
                s[nb][0] = ex2f(s[nb][0] - mn0);
                s[nb][1] = ex2f(s[nb][1] - mn0);
                s[nb][2] = ex2f(s[nb][2] - mn1);
                s[nb][3] = ex2f(s[nb][3] - mn1);
                lrow0 += s[nb][0] + s[nb][1];
                lrow1 += s[nb][2] + s[nb][3];
            }

            // ---- O += P V:  P(16x64) packed from S, V^T key-interleaved ----
#pragma unroll
            for (int kbk = 0; kbk < 4; kbk++) {     // 4 k16 blocks of keys
                const uint32_t pa0 = h2u(__floats2half2_rn(s[2*kbk][0],   s[2*kbk][1]));
                const uint32_t pa1 = h2u(__floats2half2_rn(s[2*kbk][2],   s[2*kbk][3]));
                const uint32_t pa2 = h2u(__floats2half2_rn(s[2*kbk+1][0], s[2*kbk+1][1]));
                const uint32_t pa3 = h2u(__floats2half2_rn(s[2*kbk+1][2], s[2*kbk+1][3]));
                const int vo = hf * 64 + kbk * 16 + 4 * c;
#pragma unroll
                for (int nb = 0; nb < 8; nb++) {
                    const uint2 vv = *(const uint2*)(SV + (nb * 8 + g) * VSTR + vo);
                    mma_16816_f16(o[nb], pa0, pa1, pa2, pa3, vv.x, vv.y);
                }
            }
        }
        __syncthreads();
    }

    // ---- finalize ----
    lrow0 += __shfl_xor_sync(0xffffffffu, lrow0, 1);
    lrow0 += __shfl_xor_sync(0xffffffffu, lrow0, 2);
    lrow1 += __shfl_xor_sync(0xffffffffu, lrow1, 1);
    lrow1 += __shfl_xor_sync(0xffffffffu, lrow1, 2);
    const float inv0 = 1.f / lrow0;
    const float inv1 = 1.f / lrow1;

    float* orow0 = out + ((size_t)b * TLEN + r0) * CDIM + h * HD;
    float* orow1 = out + ((size_t)b * TLEN + r1) * CDIM + h * HD;
#pragma unroll
    for (int nb = 0; nb < 8; nb++) {
        const int d = nb * 8 + 2 * c;
        *(float2*)(orow0 + d) = make_float2(o[nb][0] * inv0, o[nb][1] * inv0);
        *(float2*)(orow1 + d) = make_float2(o[nb][2] * inv1, o[nb][3] * inv1);
    }
}

// ---------------------------------------------------------------------------
extern "C" void kernel_launch(void* const* d_in, const int* in_sizes, int n_in,
                              void* d_out, int out_size)
{
    const float* x    = (const float*)d_in[0];
    const float* w    = (const float*)d_in[1];
    const float* bias = (const float*)d_in[2];
    float* out        = (float*)d_out;

    (void)in_sizes; (void)n_in; (void)out_size;

    cudaFuncSetAttribute(qkv_mma_kernel,
                         cudaFuncAttributeMaxDynamicSharedMemorySize, DYN_SMEM);
    cudaFuncSetAttribute(attn_tc_kernel,
                         cudaFuncAttributeMaxDynamicSharedMemorySize, ATTN_SMEM);

    cvt_kernel<<<592, 256>>>(w);

    dim3 ggrid(3 * CDIM / TN, (BSZ * TLEN) / TM);   // (24, 64)
    qkv_mma_kernel<<<ggrid, 256, DYN_SMEM>>>(x, bias);

    dim3 agrid(TLEN / ATM, BSZ * NHEAD);            // (16, 64)
    attn_tc_kernel<<<agrid, 256, ATTN_SMEM>>>(out);
}